// round 1
// baseline (speedup 1.0000x reference)
#include <cuda_runtime.h>
#include <cstdint>

// DbrxRouter: x[T,H] fp32 @ W[E,H]^T -> logits[T,E=16]; softmax -> top4 -> /sum(top4)
// Outputs concatenated float32: weights [T,4] then expert indices [T,4] (as float).

#define NE 16

// Packed dual-FMA (Blackwell f32x2). d.lo += a.lo*b.lo ; d.hi += a.hi*b.hi
__device__ __forceinline__ void fma2(unsigned long long& d,
                                     unsigned long long a,
                                     unsigned long long b) {
    asm("fma.rn.f32x2 %0, %1, %2, %0;" : "+l"(d) : "l"(a), "l"(b));
}

__device__ __forceinline__ float lo_f(unsigned long long v) {
    return __uint_as_float((unsigned)(v & 0xffffffffull));
}
__device__ __forceinline__ float hi_f(unsigned long long v) {
    return __uint_as_float((unsigned)(v >> 32));
}

__global__ __launch_bounds__(256, 1)
void router_kernel(const float* __restrict__ x, const float* __restrict__ w,
                   float* __restrict__ out, int T, int H4, int idx_off)
{
    const int warp = blockIdx.x * (blockDim.x >> 5) + (threadIdx.x >> 5);
    const int lane = threadIdx.x & 31;
    const int t0 = warp * 4;
    if (t0 >= T) return;

    // Clamp token rows (T divisible by 4 in practice; stay safe anyway)
    const size_t r0 = (size_t)t0 * H4;
    const size_t r1 = (size_t)min(t0 + 1, T - 1) * H4;
    const size_t r2 = (size_t)min(t0 + 2, T - 1) * H4;
    const size_t r3 = (size_t)min(t0 + 3, T - 1) * H4;

    const ulonglong2* __restrict__ x2 = reinterpret_cast<const ulonglong2*>(x);
    const ulonglong2* __restrict__ w2 = reinterpret_cast<const ulonglong2*>(w);

    // acc[t][e] is a packed f32x2 partial sum (two h-phases); combined at the end.
    unsigned long long acc[4][NE];
    #pragma unroll
    for (int t = 0; t < 4; t++)
        #pragma unroll
        for (int e = 0; e < NE; e++)
            acc[t][e] = 0ull;

    // Main loop: each lane strides the H/4 float4 row. 4 x-loads + 16 w-loads
    // feed 128 f32x2 FMAs per iteration (W bytes/FMA = 1.0, x bytes/FMA = 0.25).
    for (int i = lane; i < H4; i += 32) {
        const ulonglong2 a0 = x2[r0 + i];
        const ulonglong2 a1 = x2[r1 + i];
        const ulonglong2 a2 = x2[r2 + i];
        const ulonglong2 a3 = x2[r3 + i];
        #pragma unroll
        for (int e = 0; e < NE; e++) {
            const ulonglong2 b = w2[(size_t)e * H4 + i];
            fma2(acc[0][e], a0.x, b.x); fma2(acc[0][e], a0.y, b.y);
            fma2(acc[1][e], a1.x, b.x); fma2(acc[1][e], a1.y, b.y);
            fma2(acc[2][e], a2.x, b.x); fma2(acc[2][e], a2.y, b.y);
            fma2(acc[3][e], a3.x, b.x); fma2(acc[3][e], a3.y, b.y);
        }
    }

    // Collapse packed halves, then butterfly-reduce across the warp.
    float lg0[NE], lg1[NE], lg2[NE], lg3[NE];
    #pragma unroll
    for (int e = 0; e < NE; e++) {
        lg0[e] = lo_f(acc[0][e]) + hi_f(acc[0][e]);
        lg1[e] = lo_f(acc[1][e]) + hi_f(acc[1][e]);
        lg2[e] = lo_f(acc[2][e]) + hi_f(acc[2][e]);
        lg3[e] = lo_f(acc[3][e]) + hi_f(acc[3][e]);
    }
    #pragma unroll
    for (int off = 16; off >= 1; off >>= 1) {
        #pragma unroll
        for (int e = 0; e < NE; e++) {
            lg0[e] += __shfl_xor_sync(0xffffffffu, lg0[e], off);
            lg1[e] += __shfl_xor_sync(0xffffffffu, lg1[e], off);
            lg2[e] += __shfl_xor_sync(0xffffffffu, lg2[e], off);
            lg3[e] += __shfl_xor_sync(0xffffffffu, lg3[e], off);
        }
    }

    // Lane t (t<4) takes token t0+t. Static selects, no local-memory indexing.
    float mylg[NE];
    #pragma unroll
    for (int e = 0; e < NE; e++) {
        float v = lg0[e];
        if (lane == 1) v = lg1[e];
        if (lane == 2) v = lg2[e];
        if (lane == 3) v = lg3[e];
        mylg[e] = v;
    }

    const int token = t0 + lane;
    if (lane < 4 && token < T) {
        // Top-4 selection, stable (strict '>' picks lowest index on ties, matching jax).
        unsigned mask = 0;
        float tw[4];
        int   ti[4];
        #pragma unroll
        for (int k = 0; k < 4; k++) {
            float best = -3.402823466e38f;
            int bi = 0;
            #pragma unroll
            for (int e = 0; e < NE; e++) {
                bool ok = (((mask >> e) & 1u) == 0u) && (mylg[e] > best);
                if (ok) { best = mylg[e]; bi = e; }
            }
            tw[k] = best; ti[k] = bi;
            mask |= (1u << bi);
        }
        // Softmax denominator cancels: normalized = exp(l-m) / sum_top4 exp(l-m)
        const float m = tw[0];
        float s = 0.f;
        #pragma unroll
        for (int k = 0; k < 4; k++) { tw[k] = expf(tw[k] - m); s += tw[k]; }
        const float inv = 1.0f / s;
        #pragma unroll
        for (int k = 0; k < 4; k++) {
            out[token * 4 + k] = tw[k] * inv;
            if (idx_off >= 0) out[idx_off + token * 4 + k] = (float)ti[k];
        }
    }
}

extern "C" void kernel_launch(void* const* d_in, const int* in_sizes, int n_in,
                              void* d_out, int out_size)
{
    const float* x = (const float*)d_in[0];
    const float* w = (const float*)d_in[1];

    const int H  = in_sizes[1] / NE;     // 6144
    const int T  = in_sizes[0] / H;      // 8192
    const int H4 = H / 4;                // 1536 float4 per row

    // If out holds both tuple members (weights then indices), indices start at T*4.
    const int idx_off = (out_size >= T * 8) ? (T * 4) : -1;

    const int warps  = (T + 3) / 4;
    const int blocks = (warps + 7) / 8;  // 8 warps (256 threads) per block
    router_kernel<<<blocks, 256>>>(x, w, (float*)d_out, T, H4, idx_off);
}

// round 2
// speedup vs baseline: 1.0114x; 1.0114x over previous
#include <cuda_runtime.h>
#include <cstdint>

// DbrxRouter: x[T,H] fp32 @ W[E,H]^T -> logits[T,E=16]; softmax -> top4 -> /sum(top4)
// Outputs concatenated float32: weights [T,4] then expert indices [T,4] (as float).

#define NE 16

// Packed dual-FMA (Blackwell f32x2). d.lo += a.lo*b.lo ; d.hi += a.hi*b.hi
__device__ __forceinline__ void fma2(unsigned long long& d,
                                     unsigned long long a,
                                     unsigned long long b) {
    asm("fma.rn.f32x2 %0, %1, %2, %0;" : "+l"(d) : "l"(a), "l"(b));
}

__device__ __forceinline__ float lo_f(unsigned long long v) {
    return __uint_as_float((unsigned)(v & 0xffffffffull));
}
__device__ __forceinline__ float hi_f(unsigned long long v) {
    return __uint_as_float((unsigned)(v >> 32));
}

__global__ __launch_bounds__(256, 1)
void router_kernel(const float* __restrict__ x, const float* __restrict__ w,
                   float* __restrict__ out, int T, int H4, int idx_off)
{
    const int warp = blockIdx.x * (blockDim.x >> 5) + (threadIdx.x >> 5);
    const int lane = threadIdx.x & 31;
    const int t0 = warp * 4;
    if (t0 >= T) return;

    // Clamp token rows (T divisible by 4 in practice; stay safe anyway)
    const size_t r0 = (size_t)t0 * H4;
    const size_t r1 = (size_t)min(t0 + 1, T - 1) * H4;
    const size_t r2 = (size_t)min(t0 + 2, T - 1) * H4;
    const size_t r3 = (size_t)min(t0 + 3, T - 1) * H4;

    const ulonglong2* __restrict__ x2 = reinterpret_cast<const ulonglong2*>(x);
    const ulonglong2* __restrict__ w2 = reinterpret_cast<const ulonglong2*>(w);

    // acc[t][e] is a packed f32x2 partial sum (two h-phases); combined at the end.
    unsigned long long acc[4][NE];
    #pragma unroll
    for (int t = 0; t < 4; t++)
        #pragma unroll
        for (int e = 0; e < NE; e++)
            acc[t][e] = 0ull;

    // Main loop: each lane strides the H/4 float4 row. 4 x-loads + 16 w-loads
    // feed 128 f32x2 FMAs per iteration (W bytes/FMA = 1.0, x bytes/FMA = 0.25).
    for (int i = lane; i < H4; i += 32) {
        const ulonglong2 a0 = x2[r0 + i];
        const ulonglong2 a1 = x2[r1 + i];
        const ulonglong2 a2 = x2[r2 + i];
        const ulonglong2 a3 = x2[r3 + i];
        #pragma unroll
        for (int e = 0; e < NE; e++) {
            const ulonglong2 b = w2[(size_t)e * H4 + i];
            fma2(acc[0][e], a0.x, b.x); fma2(acc[0][e], a0.y, b.y);
            fma2(acc[1][e], a1.x, b.x); fma2(acc[1][e], a1.y, b.y);
            fma2(acc[2][e], a2.x, b.x); fma2(acc[2][e], a2.y, b.y);
            fma2(acc[3][e], a3.x, b.x); fma2(acc[3][e], a3.y, b.y);
        }
    }

    // Collapse packed halves, then butterfly-reduce across the warp.
    float lg0[NE], lg1[NE], lg2[NE], lg3[NE];
    #pragma unroll
    for (int e = 0; e < NE; e++) {
        lg0[e] = lo_f(acc[0][e]) + hi_f(acc[0][e]);
        lg1[e] = lo_f(acc[1][e]) + hi_f(acc[1][e]);
        lg2[e] = lo_f(acc[2][e]) + hi_f(acc[2][e]);
        lg3[e] = lo_f(acc[3][e]) + hi_f(acc[3][e]);
    }
    #pragma unroll
    for (int off = 16; off >= 1; off >>= 1) {
        #pragma unroll
        for (int e = 0; e < NE; e++) {
            lg0[e] += __shfl_xor_sync(0xffffffffu, lg0[e], off);
            lg1[e] += __shfl_xor_sync(0xffffffffu, lg1[e], off);
            lg2[e] += __shfl_xor_sync(0xffffffffu, lg2[e], off);
            lg3[e] += __shfl_xor_sync(0xffffffffu, lg3[e], off);
        }
    }

    // Lane t (t<4) takes token t0+t. Static selects, no local-memory indexing.
    float mylg[NE];
    #pragma unroll
    for (int e = 0; e < NE; e++) {
        float v = lg0[e];
        if (lane == 1) v = lg1[e];
        if (lane == 2) v = lg2[e];
        if (lane == 3) v = lg3[e];
        mylg[e] = v;
    }

    const int token = t0 + lane;
    if (lane < 4 && token < T) {
        // Top-4 selection, stable (strict '>' picks lowest index on ties, matching jax).
        unsigned mask = 0;
        float tw[4];
        int   ti[4];
        #pragma unroll
        for (int k = 0; k < 4; k++) {
            float best = -3.402823466e38f;
            int bi = 0;
            #pragma unroll
            for (int e = 0; e < NE; e++) {
                bool ok = (((mask >> e) & 1u) == 0u) && (mylg[e] > best);
                if (ok) { best = mylg[e]; bi = e; }
            }
            tw[k] = best; ti[k] = bi;
            mask |= (1u << bi);
        }
        // Softmax denominator cancels: normalized = exp(l-m) / sum_top4 exp(l-m)
        const float m = tw[0];
        float s = 0.f;
        #pragma unroll
        for (int k = 0; k < 4; k++) { tw[k] = expf(tw[k] - m); s += tw[k]; }
        const float inv = 1.0f / s;
        #pragma unroll
        for (int k = 0; k < 4; k++) {
            out[token * 4 + k] = tw[k] * inv;
            if (idx_off >= 0) out[idx_off + token * 4 + k] = (float)ti[k];
        }
    }
}

extern "C" void kernel_launch(void* const* d_in, const int* in_sizes, int n_in,
                              void* d_out, int out_size)
{
    const float* x = (const float*)d_in[0];
    const float* w = (const float*)d_in[1];

    const int H  = in_sizes[1] / NE;     // 6144
    const int T  = in_sizes[0] / H;      // 8192
    const int H4 = H / 4;                // 1536 float4 per row

    // If out holds both tuple members (weights then indices), indices start at T*4.
    const int idx_off = (out_size >= T * 8) ? (T * 4) : -1;

    const int warps  = (T + 3) / 4;
    const int blocks = (warps + 7) / 8;  // 8 warps (256 threads) per block
    router_kernel<<<blocks, 256>>>(x, w, (float*)d_out, T, H4, idx_off);
}